// round 13
// baseline (speedup 1.0000x reference)
#include <cuda_runtime.h>
#include <cuda_bf16.h>
#include <math.h>
#include <stdint.h>

#define DD 384
#define HH 192
#define NB 64
#define NATOMS 8192
#define IMG (DD*DD)
#define K1 256            // stage-1 folded K (208) padded to 256
#define MR 192            // rows 0..191 via GEMM; 192 special; 193..383 mirrored
#define NCHUNK 4
#define CHZ (NB / NCHUNK) // 16 batches per pipeline chunk

// ---------------- device scratch -------------------------------------------
__device__ float g_sinf[DD];
__device__ __align__(16) __nv_bfloat16 g_Cb_h[MR*K1], g_Cb_l[MR*K1];
__device__ __align__(16) __nv_bfloat16 g_Sb_h[MR*K1], g_Sb_l[MR*K1];
__device__ __align__(16) __nv_bfloat16 g_H1b_h[IMG], g_H1b_l[IMG];
__device__ __align__(16) __nv_bfloat16 g_H2b_h[IMG], g_H2b_l[IMG];
__device__ float g_H1f[IMG];
__device__ __align__(16) __nv_bfloat16 g_XeT_h[NB*DD*K1], g_XeT_l[NB*DD*K1];
__device__ __align__(16) __nv_bfloat16 g_XoT_h[NB*DD*K1], g_XoT_l[NB*DD*K1];
__device__ __align__(16) __nv_bfloat16 g_Trb_h[NB*MR*DD], g_Trb_l[NB*MR*DD];
__device__ __align__(16) __nv_bfloat16 g_Tib_h[NB*MR*DD], g_Tib_l[NB*MR*DD];
__device__ float g_T192[NB*DD];

// ---------------- helpers ----------------------------------------------------
__device__ __forceinline__ void split_bf16(float x, __nv_bfloat16& h, __nv_bfloat16& l) {
    h = __float2bfloat16_rn(x);
    l = __float2bfloat16_rn(x - __bfloat162float(h));
}
__device__ __forceinline__ uint32_t smem_u32(const void* p) {
    uint32_t a;
    asm("{ .reg .u64 t; cvta.to.shared.u64 t, %1; cvt.u32.u64 %0, t; }" : "=r"(a) : "l"(p));
    return a;
}
__device__ __forceinline__ uint32_t swz(uint32_t boff) {
    return boff ^ ((boff >> 3) & 0x70);
}
__device__ __forceinline__ void ldsm_x4(uint32_t addr, uint32_t* r) {
    asm volatile("ldmatrix.sync.aligned.m8n8.x4.shared.b16 {%0,%1,%2,%3}, [%4];"
                 : "=r"(r[0]), "=r"(r[1]), "=r"(r[2]), "=r"(r[3]) : "r"(addr));
}
__device__ __forceinline__ void ldsm_x2(uint32_t addr, uint32_t* r) {
    asm volatile("ldmatrix.sync.aligned.m8n8.x2.shared.b16 {%0,%1}, [%2];"
                 : "=r"(r[0]), "=r"(r[1]) : "r"(addr));
}
__device__ __forceinline__ void mma_bf16(float* c, const uint32_t* a, const uint32_t* b) {
    asm volatile("mma.sync.aligned.m16n8k16.row.col.f32.bf16.bf16.f32 "
                 "{%0,%1,%2,%3},{%4,%5,%6,%7},{%8,%9},{%0,%1,%2,%3};"
                 : "+f"(c[0]), "+f"(c[1]), "+f"(c[2]), "+f"(c[3])
                 : "r"(a[0]), "r"(a[1]), "r"(a[2]), "r"(a[3]), "r"(b[0]), "r"(b[1]));
}
__device__ __forceinline__ void cpasync16(uint32_t dst, const void* src) {
    asm volatile("cp.async.cg.shared.global [%0], [%1], 16;" :: "r"(dst), "l"(src));
}
#define CP_COMMIT() asm volatile("cp.async.commit_group;" ::: "memory")
#define CP_WAIT(n)  asm volatile("cp.async.wait_group %0;" :: "n"(n) : "memory")
__device__ __forceinline__ void red_v4(float* addr, float a, float b, float c, float d) {
    asm volatile("red.global.add.v4.f32 [%0], {%1,%2,%3,%4};"
                 :: "l"(addr), "f"(a), "f"(b), "f"(c), "f"(d) : "memory");
}

// ---------------- tiny sin table (double trig once) --------------------------
__global__ void sintab_kernel() {
    int i = threadIdx.x;
    if (i < DD) g_sinf[i] = (float)sin((double)i * (2.0 * M_PI / (double)DD));
}

// ---------------- all trig tables via gather ---------------------------------
__global__ void tables_kernel() {
    int i = blockIdx.x * blockDim.x + threadIdx.x;
    if (i < MR * K1) {
        int k = i >> 8, u = i & 255;
        float c = 0.f, s = 0.f;
        if (u <= 192) {
            int m = ((k + HH) * (u + HH)) % DD;
            s = g_sinf[m];
            c = g_sinf[(m + 96) % DD];
        }
        split_bf16(c, g_Cb_h[i], g_Cb_l[i]);
        split_bf16(s, g_Sb_h[i], g_Sb_l[i]);
    } else {
        int j = i - MR * K1;
        if (j >= IMG) return;
        int v = j / DD, l = j % DD;
        int m = ((v + HH) * (l + HH)) % DD;
        float s = g_sinf[m];
        float c = g_sinf[(m + 96) % DD];
        split_bf16(c + s, g_H1b_h[j], g_H1b_l[j]);
        split_bf16(c - s, g_H2b_h[j], g_H2b_l[j]);
        g_H1f[j] = c + s;
    }
}

// ---------------- splat: z-chunked, Gaussian recurrence, red.v4 --------------
__global__ void splat_kernel(const float* __restrict__ crd,
                             const float* __restrict__ rot,
                             const float* __restrict__ rot_init,
                             const float* __restrict__ trans_init,
                             float* __restrict__ img, int z0) {
    int gid = blockIdx.x * blockDim.x + threadIdx.x;
    if (z0 == 0 && gid < NB * DD) g_T192[gid] = 0.0f;
    if (gid >= CHZ * NATOMS) return;
    int b = z0 + (gid >> 13);
    int ga = b * NATOMS + (gid & (NATOMS - 1));
    const float* p = crd + (size_t)ga * 3;
    float x0 = p[0], x1 = p[1], x2 = p[2];
    float c0 = x0 * __ldg(&rot_init[0]) + x1 * __ldg(&rot_init[3]) + x2 * __ldg(&rot_init[6]) + __ldg(&trans_init[0]);
    float c1 = x0 * __ldg(&rot_init[1]) + x1 * __ldg(&rot_init[4]) + x2 * __ldg(&rot_init[7]) + __ldg(&trans_init[1]);
    float c2 = x0 * __ldg(&rot_init[2]) + x1 * __ldg(&rot_init[5]) + x2 * __ldg(&rot_init[8]) + __ldg(&trans_init[2]);
    const float* R = rot + b * 9;
    float fx = c0 * __ldg(&R[0]) + c1 * __ldg(&R[1]) + c2 * __ldg(&R[2]);
    float fy = c0 * __ldg(&R[3]) + c1 * __ldg(&R[4]) + c2 * __ldg(&R[5]);
    float cx = fx + (float)HH, cy = fy + (float)HH;
    int ix0 = (int)rintf(cx) - 5, iy0 = (int)rintf(cy) - 5;
    const float A = 1.0f / (2.0f * 1.5f * 1.5f);
    const float C2 = __expf(-2.0f * A);

    int base = ix0 & ~3;
    base = base < 0 ? 0 : (base > DD - 16 ? DD - 16 : base);

    float wx[16];
    float sq[4];
    {
        float d0 = (float)base - cx;
        float g = __expf(-A * d0 * d0);
        float m = __expf(-A * (2.0f * d0 + 1.0f));
#pragma unroll
        for (int j = 0; j < 16; j++) {
            int pos = base + j;
            bool in = (pos >= ix0) && (pos <= ix0 + 10);
            wx[j] = in ? g : 0.0f;
            g *= m;
            m *= C2;
        }
    }
    bool anyx = false;
#pragma unroll
    for (int q = 0; q < 4; q++) {
        sq[q] = wx[q*4] + wx[q*4+1] + wx[q*4+2] + wx[q*4+3];
        anyx |= (sq[q] != 0.f);
    }
    if (!anyx) return;

    float gy[11];
    {
        float e0 = (float)iy0 - cy;
        float g = __expf(-A * e0 * e0);
        float m = __expf(-A * (2.0f * e0 + 1.0f));
#pragma unroll
        for (int t = 0; t < 11; t++) {
            int iy = iy0 + t;
            gy[t] = ((unsigned)iy < (unsigned)DD) ? g : 0.0f;
            g *= m;
            m *= C2;
        }
    }

    float* im = img + (size_t)b * IMG;
#pragma unroll
    for (int ty = 0; ty < 11; ty++) {
        float gyv = gy[ty];
        if (gyv == 0.0f) continue;
        float* rowp = im + (iy0 + ty) * DD + base;
#pragma unroll
        for (int q = 0; q < 4; q++) {
            if (sq[q] != 0.f)
                red_v4(rowp + q * 4, gyv * wx[q*4], gyv * wx[q*4+1], gyv * wx[q*4+2], gyv * wx[q*4+3]);
        }
    }
}

// ---------------- fold + transpose (z-chunked) --------------------------------
__global__ void fold_kernel(const float* __restrict__ X, int z0) {
    __shared__ float se[32][33];
    __shared__ float so[32][33];
    int z = z0 + blockIdx.z;
    int u0 = blockIdx.y * 32;
    int v0 = blockIdx.x * 32;
    const float* Xb = X + (size_t)z * IMG;
#pragma unroll
    for (int r = 0; r < 4; r++) {
        int uu = u0 + threadIdx.y + r * 8;
        int vv = v0 + threadIdx.x;
        float e = 0.f, o = 0.f;
        if (uu == 0) { e = Xb[vv]; }
        else if (uu < 192) { float a = Xb[uu * DD + vv], bm = Xb[(DD - uu) * DD + vv]; e = a + bm; o = a - bm; }
        else if (uu == 192) { e = Xb[192 * DD + vv]; }
        se[threadIdx.y + r * 8][threadIdx.x] = e;
        so[threadIdx.y + r * 8][threadIdx.x] = o;
    }
    __syncthreads();
    if (threadIdx.y == 0) {
        int vv = v0 + threadIdx.x;
        float acc = 0.f;
#pragma unroll
        for (int i = 0; i < 32; i++) acc += se[i][threadIdx.x];
        if (acc != 0.f || u0 == 0) atomicAdd(&g_T192[z * DD + vv], acc);
    }
#pragma unroll
    for (int r = 0; r < 4; r++) {
        int vv = v0 + threadIdx.y + r * 8;
        int uu = u0 + threadIdx.x;
        if (uu >= 208) continue;
        float e = se[threadIdx.x][threadIdx.y + r * 8];
        float o = so[threadIdx.x][threadIdx.y + r * 8];
        size_t off = ((size_t)z * DD + vv) * K1 + uu;
        split_bf16(e, g_XeT_h[off], g_XeT_l[off]);
        split_bf16(o, g_XoT_h[off], g_XoT_l[off]);
    }
}

// ---------------- row 192 of Y ------------------------------------------------
__global__ void row192_kernel(float* __restrict__ Y) {
    int b = blockIdx.y;
    int l = blockIdx.x * blockDim.x + threadIdx.x;
    if (l >= DD) return;
    const float* t = g_T192 + b * DD;
    float acc = 0.0f;
#pragma unroll 8
    for (int v = 0; v < DD; v++) acc += t[v] * g_H1f[v * DD + l];
    Y[(size_t)b * IMG + 192 * DD + l] = acc;
}

// ---------------- generic split-precision HMMA GEMM, cp.async 2-stage -------
#define STG 98304u
template<int MODE>
__global__ __launch_bounds__(256, 1) void mma_gemm_kernel(float* __restrict__ Y, int z0) {
    extern __shared__ char smem[];
    uint32_t sb = smem_u32(smem);
    const int t = threadIdx.x;
    const int lane = t & 31, wid = t >> 5;
    const int wm = wid >> 2, wn = wid & 3;
    const int z = z0 + blockIdx.z, m0 = blockIdx.y * 64, n0 = blockIdx.x * 128;

    const int KCH = (MODE == 0) ? 4 : 6;
    const int LD  = (MODE == 0) ? K1 : DD;

    const __nv_bfloat16* Asrc[4];
    const __nv_bfloat16* Bsrc[4];
    if (MODE == 0) {
        Asrc[0] = g_Cb_h + (size_t)m0 * K1;  Asrc[1] = g_Cb_l + (size_t)m0 * K1;
        Asrc[2] = g_Sb_h + (size_t)m0 * K1;  Asrc[3] = g_Sb_l + (size_t)m0 * K1;
        size_t bo = ((size_t)z * DD + n0) * K1;
        Bsrc[0] = g_XeT_h + bo; Bsrc[1] = g_XeT_l + bo;
        Bsrc[2] = g_XoT_h + bo; Bsrc[3] = g_XoT_l + bo;
    } else {
        size_t ao = ((size_t)z * MR + m0) * DD;
        Asrc[0] = g_Trb_h + ao; Asrc[1] = g_Trb_l + ao;
        Asrc[2] = g_Tib_h + ao; Asrc[3] = g_Tib_l + ao;
        size_t bo = (size_t)n0 * DD;
        Bsrc[0] = g_H1b_h + bo; Bsrc[1] = g_H1b_l + bo;
        Bsrc[2] = g_H2b_h + bo; Bsrc[3] = g_H2b_l + bo;
    }

    auto stage = [&](uint32_t buf, int kc) {
#pragma unroll
        for (int s = 0; s < 4; s++) {
#pragma unroll
            for (int j = 0; j < 2; j++) {
                int cid = t + 256 * j;
                int row = cid >> 3, c = cid & 7;
                cpasync16(buf + s * 8192u + swz((uint32_t)row * 128u + (uint32_t)c * 16u),
                          Asrc[s] + (size_t)row * LD + kc * 64 + c * 8);
            }
#pragma unroll
            for (int j = 0; j < 4; j++) {
                int cid = t + 256 * j;
                int row = cid >> 3, c = cid & 7;
                cpasync16(buf + 32768u + s * 16384u + swz((uint32_t)row * 128u + (uint32_t)c * 16u),
                          Bsrc[s] + (size_t)row * LD + kc * 64 + c * 8);
            }
        }
    };

    float acc[2][2][4][4];
#pragma unroll
    for (int o = 0; o < 2; o++)
#pragma unroll
        for (int mt = 0; mt < 2; mt++)
#pragma unroll
            for (int nt = 0; nt < 4; nt++)
#pragma unroll
                for (int r = 0; r < 4; r++) acc[o][mt][nt][r] = 0.f;

    const int a_row = wm * 32 + (lane & 7) + ((lane >> 3) & 1) * 8;
    const int a_kb  = (lane >> 4) * 16;
    const int b_row = wn * 32 + (lane & 7);
    const int b_kb  = (((lane & 15) >> 3)) * 16;

    stage(sb, 0);
    CP_COMMIT();

    for (int kc = 0; kc < KCH; kc++) {
        uint32_t cur = sb + (uint32_t)(kc & 1) * STG;
        if (kc + 1 < KCH) {
            stage(sb + (uint32_t)((kc + 1) & 1) * STG, kc + 1);
            CP_COMMIT();
            CP_WAIT(1);
        } else {
            CP_WAIT(0);
        }
        __syncthreads();

#pragma unroll
        for (int k16 = 0; k16 < 4; k16++) {
            uint32_t a[4][2][4], b[4][4][2];
#pragma unroll
            for (int s = 0; s < 4; s++)
#pragma unroll
                for (int mt = 0; mt < 2; mt++) {
                    uint32_t bo = (uint32_t)(a_row + mt * 16) * 128u + (uint32_t)(k16 * 32 + a_kb);
                    ldsm_x4(cur + s * 8192u + swz(bo), a[s][mt]);
                }
#pragma unroll
            for (int s = 0; s < 4; s++)
#pragma unroll
                for (int nt = 0; nt < 4; nt++) {
                    uint32_t bo = (uint32_t)(b_row + nt * 8) * 128u + (uint32_t)(k16 * 32 + b_kb);
                    ldsm_x2(cur + 32768u + s * 16384u + swz(bo), b[s][nt]);
                }
#pragma unroll
            for (int mt = 0; mt < 2; mt++)
#pragma unroll
                for (int nt = 0; nt < 4; nt++) {
                    mma_bf16(acc[0][mt][nt], a[0][mt], b[0][nt]);
                    mma_bf16(acc[0][mt][nt], a[0][mt], b[1][nt]);
                    mma_bf16(acc[0][mt][nt], a[1][mt], b[0][nt]);
                    mma_bf16(acc[1][mt][nt], a[2][mt], b[2][nt]);
                    mma_bf16(acc[1][mt][nt], a[2][mt], b[3][nt]);
                    mma_bf16(acc[1][mt][nt], a[3][mt], b[2][nt]);
                }
        }
        __syncthreads();
    }

    const int gr = lane >> 2, gc = 2 * (lane & 3);
    if (MODE == 0) {
#pragma unroll
        for (int mt = 0; mt < 2; mt++)
#pragma unroll
            for (int nt = 0; nt < 4; nt++) {
                int col = n0 + wn * 32 + nt * 8 + gc;
#pragma unroll
                for (int h = 0; h < 2; h++) {
                    int row = m0 + wm * 32 + mt * 16 + gr + h * 8;
                    size_t off = ((size_t)z * MR + row) * DD + col;
                    __nv_bfloat16 h0, l0, h1, l1;
                    split_bf16(acc[0][mt][nt][h * 2],     h0, l0);
                    split_bf16(acc[0][mt][nt][h * 2 + 1], h1, l1);
                    __nv_bfloat162 hh; hh.x = h0; hh.y = h1;
                    __nv_bfloat162 ll; ll.x = l0; ll.y = l1;
                    *reinterpret_cast<__nv_bfloat162*>(&g_Trb_h[off]) = hh;
                    *reinterpret_cast<__nv_bfloat162*>(&g_Trb_l[off]) = ll;
                    split_bf16(acc[1][mt][nt][h * 2],     h0, l0);
                    split_bf16(acc[1][mt][nt][h * 2 + 1], h1, l1);
                    hh.x = h0; hh.y = h1; ll.x = l0; ll.y = l1;
                    *reinterpret_cast<__nv_bfloat162*>(&g_Tib_h[off]) = hh;
                    *reinterpret_cast<__nv_bfloat162*>(&g_Tib_l[off]) = ll;
                }
            }
    } else {
        float* Yb = Y + (size_t)z * IMG;
#pragma unroll
        for (int mt = 0; mt < 2; mt++)
#pragma unroll
            for (int nt = 0; nt < 4; nt++) {
                int col = n0 + wn * 32 + nt * 8 + gc;
#pragma unroll
                for (int h = 0; h < 2; h++) {
                    int row = m0 + wm * 32 + mt * 16 + gr + h * 8;
                    float p0 = acc[0][mt][nt][h * 2],     q0 = acc[1][mt][nt][h * 2];
                    float p1 = acc[0][mt][nt][h * 2 + 1], q1 = acc[1][mt][nt][h * 2 + 1];
                    float2 yp; yp.x = p0 + q0; yp.y = p1 + q1;
                    *reinterpret_cast<float2*>(&Yb[(size_t)row * DD + col]) = yp;
                    if (row >= 1) {
                        float2 ym; ym.x = p0 - q0; ym.y = p1 - q1;
                        *reinterpret_cast<float2*>(&Yb[(size_t)(DD - row) * DD + col]) = ym;
                    }
                }
            }
    }
}

#define SMEM_BYTES (2 * 98304)

// ---------------------------------------------------------------------------
extern "C" void kernel_launch(void* const* d_in, const int* in_sizes, int n_in,
                              void* d_out, int out_size) {
    const float* crd = nullptr;
    const float* rot = nullptr;
    const float* rot_init = nullptr;
    const float* trans_init = nullptr;
    for (int i = 0; i < n_in; i++) {
        switch (in_sizes[i]) {
            case 1572864: crd        = (const float*)d_in[i]; break;
            case 576:     rot        = (const float*)d_in[i]; break;
            case 9:       rot_init   = (const float*)d_in[i]; break;
            case 3:       trans_init = (const float*)d_in[i]; break;
            default: break;
        }
    }

    float* y = (float*)d_out;
    size_t half = (size_t)out_size / 2;   // 64*384*384
    float* y_real = y + half;

    cudaFuncSetAttribute(mma_gemm_kernel<0>, cudaFuncAttributeMaxDynamicSharedMemorySize, SMEM_BYTES);
    cudaFuncSetAttribute(mma_gemm_kernel<1>, cudaFuncAttributeMaxDynamicSharedMemorySize, SMEM_BYTES);

    cudaStream_t s2;
    cudaStreamCreateWithFlags(&s2, cudaStreamNonBlocking);
    cudaEvent_t ev_fork, ev_fold[NCHUNK], ev_done;
    cudaEventCreateWithFlags(&ev_fork, cudaEventDisableTiming);
    cudaEventCreateWithFlags(&ev_done, cudaEventDisableTiming);
    for (int c = 0; c < NCHUNK; c++)
        cudaEventCreateWithFlags(&ev_fold[c], cudaEventDisableTiming);

    cudaMemsetAsync(y_real, 0, half * sizeof(float));

    // fork: tables on s2 (needed only by gemms / row192)
    cudaEventRecord(ev_fork, (cudaStream_t)0);
    cudaStreamWaitEvent(s2, ev_fork, 0);
    sintab_kernel<<<1, 384, 0, s2>>>();
    tables_kernel<<<(MR * K1 + IMG + 255) / 256, 256, 0, s2>>>();

    // z-chunked pipeline: stream0 = splat_c -> fold_c ; s2 = gemm0_c -> gemm1_c
    dim3 gf(DD / 32, 7, CHZ);
    dim3 gg(DD / 128, MR / 64, CHZ);
    for (int c = 0; c < NCHUNK; c++) {
        int z0 = c * CHZ;
        splat_kernel<<<(CHZ * NATOMS + 255) / 256, 256>>>(crd, rot, rot_init, trans_init, y_real, z0);
        fold_kernel<<<gf, dim3(32, 8)>>>(y_real, z0);
        cudaEventRecord(ev_fold[c], (cudaStream_t)0);
        cudaStreamWaitEvent(s2, ev_fold[c], 0);
        mma_gemm_kernel<0><<<gg, 256, SMEM_BYTES, s2>>>(nullptr, z0);
        mma_gemm_kernel<1><<<gg, 256, SMEM_BYTES, s2>>>(y, z0);
    }

    // row192 on stream0 after last fold (needs all T192 + H1f); runs under s2 gemms.
    // stream0 must also see tables (H1f): reuse ev_fold mechanism — tables finished
    // long before; enforce explicitly via event from s2 recorded after tables.
    // (tables end precedes gemm0_0 on s2; gemm1 chunk 0 completion implies tables done,
    //  but row192 may start earlier — gate it on a dedicated event.)
    cudaEvent_t ev_tab;
    cudaEventCreateWithFlags(&ev_tab, cudaEventDisableTiming);
    // NOTE: event recorded here captures s2 state AFTER the enqueued gemm chunk 0+ work
    // only if recorded earlier; record right after tables would be ideal but we are past
    // that point in code — instead gate row192 on ev_done ordering below is wrong.
    // Simplest correct: row192 on s2 at the end (tables + all folds visible there).
    for (int c = 0; c < NCHUNK; c++) { /* folds already waited on s2 via ev_fold */ }
    dim3 gr((DD + 127) / 128, NB);
    row192_kernel<<<gr, 128, 0, s2>>>(y);

    // join s2 back into stream0
    cudaEventRecord(ev_done, s2);
    cudaStreamWaitEvent((cudaStream_t)0, ev_done, 0);

    cudaStreamDestroy(s2);
    cudaEventDestroy(ev_fork);
    cudaEventDestroy(ev_done);
    cudaEventDestroy(ev_tab);
    for (int c = 0; c < NCHUNK; c++) cudaEventDestroy(ev_fold[c]);
}

// round 14
// speedup vs baseline: 1.0223x; 1.0223x over previous
#include <cuda_runtime.h>
#include <cuda_bf16.h>
#include <math.h>
#include <stdint.h>

#define DD 384
#define HH 192
#define NB 64
#define NATOMS 8192
#define IMG (DD*DD)
#define K1 256            // stage-1 folded K (208) padded to 256
#define MR 192            // rows 0..191 via GEMM; 192 special; 193..383 mirrored
#define NCHUNK 2
#define CHZ (NB / NCHUNK) // 32 batches per pipeline chunk

// ---------------- device scratch -------------------------------------------
__device__ float g_sinf[DD];
__device__ __align__(16) __nv_bfloat16 g_Cb_h[MR*K1], g_Cb_l[MR*K1];
__device__ __align__(16) __nv_bfloat16 g_Sb_h[MR*K1], g_Sb_l[MR*K1];
__device__ __align__(16) __nv_bfloat16 g_H1b_h[IMG], g_H1b_l[IMG];
__device__ __align__(16) __nv_bfloat16 g_H2b_h[IMG], g_H2b_l[IMG];
__device__ float g_H1f[IMG];
__device__ __align__(16) __nv_bfloat16 g_XeT_h[NB*DD*K1], g_XeT_l[NB*DD*K1];
__device__ __align__(16) __nv_bfloat16 g_XoT_h[NB*DD*K1], g_XoT_l[NB*DD*K1];
__device__ __align__(16) __nv_bfloat16 g_Trb_h[NB*MR*DD], g_Trb_l[NB*MR*DD];
__device__ __align__(16) __nv_bfloat16 g_Tib_h[NB*MR*DD], g_Tib_l[NB*MR*DD];
__device__ float g_T192[NB*DD];

// ---------------- helpers ----------------------------------------------------
__device__ __forceinline__ void split_bf16(float x, __nv_bfloat16& h, __nv_bfloat16& l) {
    h = __float2bfloat16_rn(x);
    l = __float2bfloat16_rn(x - __bfloat162float(h));
}
__device__ __forceinline__ uint32_t smem_u32(const void* p) {
    uint32_t a;
    asm("{ .reg .u64 t; cvta.to.shared.u64 t, %1; cvt.u32.u64 %0, t; }" : "=r"(a) : "l"(p));
    return a;
}
__device__ __forceinline__ uint32_t swz(uint32_t boff) {
    return boff ^ ((boff >> 3) & 0x70);
}
__device__ __forceinline__ void ldsm_x4(uint32_t addr, uint32_t* r) {
    asm volatile("ldmatrix.sync.aligned.m8n8.x4.shared.b16 {%0,%1,%2,%3}, [%4];"
                 : "=r"(r[0]), "=r"(r[1]), "=r"(r[2]), "=r"(r[3]) : "r"(addr));
}
__device__ __forceinline__ void ldsm_x2(uint32_t addr, uint32_t* r) {
    asm volatile("ldmatrix.sync.aligned.m8n8.x2.shared.b16 {%0,%1}, [%2];"
                 : "=r"(r[0]), "=r"(r[1]) : "r"(addr));
}
__device__ __forceinline__ void mma_bf16(float* c, const uint32_t* a, const uint32_t* b) {
    asm volatile("mma.sync.aligned.m16n8k16.row.col.f32.bf16.bf16.f32 "
                 "{%0,%1,%2,%3},{%4,%5,%6,%7},{%8,%9},{%0,%1,%2,%3};"
                 : "+f"(c[0]), "+f"(c[1]), "+f"(c[2]), "+f"(c[3])
                 : "r"(a[0]), "r"(a[1]), "r"(a[2]), "r"(a[3]), "r"(b[0]), "r"(b[1]));
}
__device__ __forceinline__ void cpasync16(uint32_t dst, const void* src) {
    asm volatile("cp.async.cg.shared.global [%0], [%1], 16;" :: "r"(dst), "l"(src));
}
#define CP_COMMIT() asm volatile("cp.async.commit_group;" ::: "memory")
#define CP_WAIT(n)  asm volatile("cp.async.wait_group %0;" :: "n"(n) : "memory")
__device__ __forceinline__ void red_v4(float* addr, float a, float b, float c, float d) {
    asm volatile("red.global.add.v4.f32 [%0], {%1,%2,%3,%4};"
                 :: "l"(addr), "f"(a), "f"(b), "f"(c), "f"(d) : "memory");
}

// ---------------- tiny sin table (double trig once) --------------------------
__global__ void sintab_kernel() {
    int i = threadIdx.x;
    if (i < DD) g_sinf[i] = (float)sin((double)i * (2.0 * M_PI / (double)DD));
}

// ---------------- all trig tables via gather ---------------------------------
__global__ void tables_kernel() {
    int i = blockIdx.x * blockDim.x + threadIdx.x;
    if (i < MR * K1) {
        int k = i >> 8, u = i & 255;
        float c = 0.f, s = 0.f;
        if (u <= 192) {
            int m = ((k + HH) * (u + HH)) % DD;
            s = g_sinf[m];
            c = g_sinf[(m + 96) % DD];
        }
        split_bf16(c, g_Cb_h[i], g_Cb_l[i]);
        split_bf16(s, g_Sb_h[i], g_Sb_l[i]);
    } else {
        int j = i - MR * K1;
        if (j >= IMG) return;
        int v = j / DD, l = j % DD;
        int m = ((v + HH) * (l + HH)) % DD;
        float s = g_sinf[m];
        float c = g_sinf[(m + 96) % DD];
        split_bf16(c + s, g_H1b_h[j], g_H1b_l[j]);
        split_bf16(c - s, g_H2b_h[j], g_H2b_l[j]);
        g_H1f[j] = c + s;
    }
}

// ---------------- splat: z-chunked, Gaussian recurrence, red.v4 --------------
__global__ void splat_kernel(const float* __restrict__ crd,
                             const float* __restrict__ rot,
                             const float* __restrict__ rot_init,
                             const float* __restrict__ trans_init,
                             float* __restrict__ img, int z0) {
    int gid = blockIdx.x * blockDim.x + threadIdx.x;
    if (z0 == 0 && gid < NB * DD) g_T192[gid] = 0.0f;
    if (gid >= CHZ * NATOMS) return;
    int b = z0 + (gid >> 13);
    int ga = b * NATOMS + (gid & (NATOMS - 1));
    const float* p = crd + (size_t)ga * 3;
    float x0 = p[0], x1 = p[1], x2 = p[2];
    float c0 = x0 * __ldg(&rot_init[0]) + x1 * __ldg(&rot_init[3]) + x2 * __ldg(&rot_init[6]) + __ldg(&trans_init[0]);
    float c1 = x0 * __ldg(&rot_init[1]) + x1 * __ldg(&rot_init[4]) + x2 * __ldg(&rot_init[7]) + __ldg(&trans_init[1]);
    float c2 = x0 * __ldg(&rot_init[2]) + x1 * __ldg(&rot_init[5]) + x2 * __ldg(&rot_init[8]) + __ldg(&trans_init[2]);
    const float* R = rot + b * 9;
    float fx = c0 * __ldg(&R[0]) + c1 * __ldg(&R[1]) + c2 * __ldg(&R[2]);
    float fy = c0 * __ldg(&R[3]) + c1 * __ldg(&R[4]) + c2 * __ldg(&R[5]);
    float cx = fx + (float)HH, cy = fy + (float)HH;
    int ix0 = (int)rintf(cx) - 5, iy0 = (int)rintf(cy) - 5;
    const float A = 1.0f / (2.0f * 1.5f * 1.5f);
    const float C2 = __expf(-2.0f * A);

    int base = ix0 & ~3;
    base = base < 0 ? 0 : (base > DD - 16 ? DD - 16 : base);

    float wx[16];
    float sq[4];
    {
        float d0 = (float)base - cx;
        float g = __expf(-A * d0 * d0);
        float m = __expf(-A * (2.0f * d0 + 1.0f));
#pragma unroll
        for (int j = 0; j < 16; j++) {
            int pos = base + j;
            bool in = (pos >= ix0) && (pos <= ix0 + 10);
            wx[j] = in ? g : 0.0f;
            g *= m;
            m *= C2;
        }
    }
    bool anyx = false;
#pragma unroll
    for (int q = 0; q < 4; q++) {
        sq[q] = wx[q*4] + wx[q*4+1] + wx[q*4+2] + wx[q*4+3];
        anyx |= (sq[q] != 0.f);
    }
    if (!anyx) return;

    float gy[11];
    {
        float e0 = (float)iy0 - cy;
        float g = __expf(-A * e0 * e0);
        float m = __expf(-A * (2.0f * e0 + 1.0f));
#pragma unroll
        for (int t = 0; t < 11; t++) {
            int iy = iy0 + t;
            gy[t] = ((unsigned)iy < (unsigned)DD) ? g : 0.0f;
            g *= m;
            m *= C2;
        }
    }

    float* im = img + (size_t)b * IMG;
#pragma unroll
    for (int ty = 0; ty < 11; ty++) {
        float gyv = gy[ty];
        if (gyv == 0.0f) continue;
        float* rowp = im + (iy0 + ty) * DD + base;
#pragma unroll
        for (int q = 0; q < 4; q++) {
            if (sq[q] != 0.f)
                red_v4(rowp + q * 4, gyv * wx[q*4], gyv * wx[q*4+1], gyv * wx[q*4+2], gyv * wx[q*4+3]);
        }
    }
}

// ---------------- fold + transpose (z-chunked) --------------------------------
__global__ void fold_kernel(const float* __restrict__ X, int z0) {
    __shared__ float se[32][33];
    __shared__ float so[32][33];
    int z = z0 + blockIdx.z;
    int u0 = blockIdx.y * 32;
    int v0 = blockIdx.x * 32;
    const float* Xb = X + (size_t)z * IMG;
#pragma unroll
    for (int r = 0; r < 4; r++) {
        int uu = u0 + threadIdx.y + r * 8;
        int vv = v0 + threadIdx.x;
        float e = 0.f, o = 0.f;
        if (uu == 0) { e = Xb[vv]; }
        else if (uu < 192) { float a = Xb[uu * DD + vv], bm = Xb[(DD - uu) * DD + vv]; e = a + bm; o = a - bm; }
        else if (uu == 192) { e = Xb[192 * DD + vv]; }
        se[threadIdx.y + r * 8][threadIdx.x] = e;
        so[threadIdx.y + r * 8][threadIdx.x] = o;
    }
    __syncthreads();
    if (threadIdx.y == 0) {
        int vv = v0 + threadIdx.x;
        float acc = 0.f;
#pragma unroll
        for (int i = 0; i < 32; i++) acc += se[i][threadIdx.x];
        if (acc != 0.f || u0 == 0) atomicAdd(&g_T192[z * DD + vv], acc);
    }
#pragma unroll
    for (int r = 0; r < 4; r++) {
        int vv = v0 + threadIdx.y + r * 8;
        int uu = u0 + threadIdx.x;
        if (uu >= 208) continue;
        float e = se[threadIdx.x][threadIdx.y + r * 8];
        float o = so[threadIdx.x][threadIdx.y + r * 8];
        size_t off = ((size_t)z * DD + vv) * K1 + uu;
        split_bf16(e, g_XeT_h[off], g_XeT_l[off]);
        split_bf16(o, g_XoT_h[off], g_XoT_l[off]);
    }
}

// ---------------- row 192 of Y ------------------------------------------------
__global__ void row192_kernel(float* __restrict__ Y) {
    int b = blockIdx.y;
    int l = blockIdx.x * blockDim.x + threadIdx.x;
    if (l >= DD) return;
    const float* t = g_T192 + b * DD;
    float acc = 0.0f;
#pragma unroll 8
    for (int v = 0; v < DD; v++) acc += t[v] * g_H1f[v * DD + l];
    Y[(size_t)b * IMG + 192 * DD + l] = acc;
}

// ---------------- generic split-precision HMMA GEMM, cp.async 2-stage -------
#define STG 98304u
template<int MODE>
__global__ __launch_bounds__(256, 1) void mma_gemm_kernel(float* __restrict__ Y, int z0) {
    extern __shared__ char smem[];
    uint32_t sb = smem_u32(smem);
    const int t = threadIdx.x;
    const int lane = t & 31, wid = t >> 5;
    const int wm = wid >> 2, wn = wid & 3;
    const int z = z0 + blockIdx.z, m0 = blockIdx.y * 64, n0 = blockIdx.x * 128;

    const int KCH = (MODE == 0) ? 4 : 6;
    const int LD  = (MODE == 0) ? K1 : DD;

    const __nv_bfloat16* Asrc[4];
    const __nv_bfloat16* Bsrc[4];
    if (MODE == 0) {
        Asrc[0] = g_Cb_h + (size_t)m0 * K1;  Asrc[1] = g_Cb_l + (size_t)m0 * K1;
        Asrc[2] = g_Sb_h + (size_t)m0 * K1;  Asrc[3] = g_Sb_l + (size_t)m0 * K1;
        size_t bo = ((size_t)z * DD + n0) * K1;
        Bsrc[0] = g_XeT_h + bo; Bsrc[1] = g_XeT_l + bo;
        Bsrc[2] = g_XoT_h + bo; Bsrc[3] = g_XoT_l + bo;
    } else {
        size_t ao = ((size_t)z * MR + m0) * DD;
        Asrc[0] = g_Trb_h + ao; Asrc[1] = g_Trb_l + ao;
        Asrc[2] = g_Tib_h + ao; Asrc[3] = g_Tib_l + ao;
        size_t bo = (size_t)n0 * DD;
        Bsrc[0] = g_H1b_h + bo; Bsrc[1] = g_H1b_l + bo;
        Bsrc[2] = g_H2b_h + bo; Bsrc[3] = g_H2b_l + bo;
    }

    auto stage = [&](uint32_t buf, int kc) {
#pragma unroll
        for (int s = 0; s < 4; s++) {
#pragma unroll
            for (int j = 0; j < 2; j++) {
                int cid = t + 256 * j;
                int row = cid >> 3, c = cid & 7;
                cpasync16(buf + s * 8192u + swz((uint32_t)row * 128u + (uint32_t)c * 16u),
                          Asrc[s] + (size_t)row * LD + kc * 64 + c * 8);
            }
#pragma unroll
            for (int j = 0; j < 4; j++) {
                int cid = t + 256 * j;
                int row = cid >> 3, c = cid & 7;
                cpasync16(buf + 32768u + s * 16384u + swz((uint32_t)row * 128u + (uint32_t)c * 16u),
                          Bsrc[s] + (size_t)row * LD + kc * 64 + c * 8);
            }
        }
    };

    float acc[2][2][4][4];
#pragma unroll
    for (int o = 0; o < 2; o++)
#pragma unroll
        for (int mt = 0; mt < 2; mt++)
#pragma unroll
            for (int nt = 0; nt < 4; nt++)
#pragma unroll
                for (int r = 0; r < 4; r++) acc[o][mt][nt][r] = 0.f;

    const int a_row = wm * 32 + (lane & 7) + ((lane >> 3) & 1) * 8;
    const int a_kb  = (lane >> 4) * 16;
    const int b_row = wn * 32 + (lane & 7);
    const int b_kb  = (((lane & 15) >> 3)) * 16;

    stage(sb, 0);
    CP_COMMIT();

    for (int kc = 0; kc < KCH; kc++) {
        uint32_t cur = sb + (uint32_t)(kc & 1) * STG;
        if (kc + 1 < KCH) {
            stage(sb + (uint32_t)((kc + 1) & 1) * STG, kc + 1);
            CP_COMMIT();
            CP_WAIT(1);
        } else {
            CP_WAIT(0);
        }
        __syncthreads();

#pragma unroll
        for (int k16 = 0; k16 < 4; k16++) {
            uint32_t a[4][2][4], b[4][4][2];
#pragma unroll
            for (int s = 0; s < 4; s++)
#pragma unroll
                for (int mt = 0; mt < 2; mt++) {
                    uint32_t bo = (uint32_t)(a_row + mt * 16) * 128u + (uint32_t)(k16 * 32 + a_kb);
                    ldsm_x4(cur + s * 8192u + swz(bo), a[s][mt]);
                }
#pragma unroll
            for (int s = 0; s < 4; s++)
#pragma unroll
                for (int nt = 0; nt < 4; nt++) {
                    uint32_t bo = (uint32_t)(b_row + nt * 8) * 128u + (uint32_t)(k16 * 32 + b_kb);
                    ldsm_x2(cur + 32768u + s * 16384u + swz(bo), b[s][nt]);
                }
#pragma unroll
            for (int mt = 0; mt < 2; mt++)
#pragma unroll
                for (int nt = 0; nt < 4; nt++) {
                    mma_bf16(acc[0][mt][nt], a[0][mt], b[0][nt]);
                    mma_bf16(acc[0][mt][nt], a[0][mt], b[1][nt]);
                    mma_bf16(acc[0][mt][nt], a[1][mt], b[0][nt]);
                    mma_bf16(acc[1][mt][nt], a[2][mt], b[2][nt]);
                    mma_bf16(acc[1][mt][nt], a[2][mt], b[3][nt]);
                    mma_bf16(acc[1][mt][nt], a[3][mt], b[2][nt]);
                }
        }
        __syncthreads();
    }

    const int gr = lane >> 2, gc = 2 * (lane & 3);
    if (MODE == 0) {
#pragma unroll
        for (int mt = 0; mt < 2; mt++)
#pragma unroll
            for (int nt = 0; nt < 4; nt++) {
                int col = n0 + wn * 32 + nt * 8 + gc;
#pragma unroll
                for (int h = 0; h < 2; h++) {
                    int row = m0 + wm * 32 + mt * 16 + gr + h * 8;
                    size_t off = ((size_t)z * MR + row) * DD + col;
                    __nv_bfloat16 h0, l0, h1, l1;
                    split_bf16(acc[0][mt][nt][h * 2],     h0, l0);
                    split_bf16(acc[0][mt][nt][h * 2 + 1], h1, l1);
                    __nv_bfloat162 hh; hh.x = h0; hh.y = h1;
                    __nv_bfloat162 ll; ll.x = l0; ll.y = l1;
                    *reinterpret_cast<__nv_bfloat162*>(&g_Trb_h[off]) = hh;
                    *reinterpret_cast<__nv_bfloat162*>(&g_Trb_l[off]) = ll;
                    split_bf16(acc[1][mt][nt][h * 2],     h0, l0);
                    split_bf16(acc[1][mt][nt][h * 2 + 1], h1, l1);
                    hh.x = h0; hh.y = h1; ll.x = l0; ll.y = l1;
                    *reinterpret_cast<__nv_bfloat162*>(&g_Tib_h[off]) = hh;
                    *reinterpret_cast<__nv_bfloat162*>(&g_Tib_l[off]) = ll;
                }
            }
    } else {
        float* Yb = Y + (size_t)z * IMG;
#pragma unroll
        for (int mt = 0; mt < 2; mt++)
#pragma unroll
            for (int nt = 0; nt < 4; nt++) {
                int col = n0 + wn * 32 + nt * 8 + gc;
#pragma unroll
                for (int h = 0; h < 2; h++) {
                    int row = m0 + wm * 32 + mt * 16 + gr + h * 8;
                    float p0 = acc[0][mt][nt][h * 2],     q0 = acc[1][mt][nt][h * 2];
                    float p1 = acc[0][mt][nt][h * 2 + 1], q1 = acc[1][mt][nt][h * 2 + 1];
                    float2 yp; yp.x = p0 + q0; yp.y = p1 + q1;
                    *reinterpret_cast<float2*>(&Yb[(size_t)row * DD + col]) = yp;
                    if (row >= 1) {
                        float2 ym; ym.x = p0 - q0; ym.y = p1 - q1;
                        *reinterpret_cast<float2*>(&Yb[(size_t)(DD - row) * DD + col]) = ym;
                    }
                }
            }
    }
}

#define SMEM_BYTES (2 * 98304)

// ---------------------------------------------------------------------------
extern "C" void kernel_launch(void* const* d_in, const int* in_sizes, int n_in,
                              void* d_out, int out_size) {
    const float* crd = nullptr;
    const float* rot = nullptr;
    const float* rot_init = nullptr;
    const float* trans_init = nullptr;
    for (int i = 0; i < n_in; i++) {
        switch (in_sizes[i]) {
            case 1572864: crd        = (const float*)d_in[i]; break;
            case 576:     rot        = (const float*)d_in[i]; break;
            case 9:       rot_init   = (const float*)d_in[i]; break;
            case 3:       trans_init = (const float*)d_in[i]; break;
            default: break;
        }
    }

    float* y = (float*)d_out;
    size_t half = (size_t)out_size / 2;   // 64*384*384
    float* y_real = y + half;

    cudaFuncSetAttribute(mma_gemm_kernel<0>, cudaFuncAttributeMaxDynamicSharedMemorySize, SMEM_BYTES);
    cudaFuncSetAttribute(mma_gemm_kernel<1>, cudaFuncAttributeMaxDynamicSharedMemorySize, SMEM_BYTES);

    cudaStream_t s2;
    cudaStreamCreateWithFlags(&s2, cudaStreamNonBlocking);
    cudaEvent_t ev_fork, ev_fold[NCHUNK], ev_done;
    cudaEventCreateWithFlags(&ev_fork, cudaEventDisableTiming);
    cudaEventCreateWithFlags(&ev_done, cudaEventDisableTiming);
    for (int c = 0; c < NCHUNK; c++)
        cudaEventCreateWithFlags(&ev_fold[c], cudaEventDisableTiming);

    cudaMemsetAsync(y_real, 0, half * sizeof(float));

    // fork: tables on s2 (consumed only by gemms / row192, all on s2)
    cudaEventRecord(ev_fork, (cudaStream_t)0);
    cudaStreamWaitEvent(s2, ev_fork, 0);
    sintab_kernel<<<1, 384, 0, s2>>>();
    tables_kernel<<<(MR * K1 + IMG + 255) / 256, 256, 0, s2>>>();

    // 2-chunk pipeline: stream0 = splat_c -> fold_c ; s2 = gemm0_c -> gemm1_c
    dim3 gf(DD / 32, 7, CHZ);
    dim3 gg(DD / 128, MR / 64, CHZ);          // 3 x 3 x 32 = 288 CTAs (~2 waves)
    for (int c = 0; c < NCHUNK; c++) {
        int z0 = c * CHZ;
        splat_kernel<<<(CHZ * NATOMS + 255) / 256, 256>>>(crd, rot, rot_init, trans_init, y_real, z0);
        fold_kernel<<<gf, dim3(32, 8)>>>(y_real, z0);
        cudaEventRecord(ev_fold[c], (cudaStream_t)0);
        cudaStreamWaitEvent(s2, ev_fold[c], 0);
        mma_gemm_kernel<0><<<gg, 256, SMEM_BYTES, s2>>>(nullptr, z0);
        mma_gemm_kernel<1><<<gg, 256, SMEM_BYTES, s2>>>(y, z0);
    }

    // row192 on s2: sees tables + all folds (via the per-chunk event waits)
    dim3 gr((DD + 127) / 128, NB);
    row192_kernel<<<gr, 128, 0, s2>>>(y);

    // join
    cudaEventRecord(ev_done, s2);
    cudaStreamWaitEvent((cudaStream_t)0, ev_done, 0);

    cudaStreamDestroy(s2);
    cudaEventDestroy(ev_fork);
    cudaEventDestroy(ev_done);
    for (int c = 0; c < NCHUNK; c++) cudaEventDestroy(ev_fold[c]);
}

// round 15
// speedup vs baseline: 1.0624x; 1.0392x over previous
#include <cuda_runtime.h>
#include <cuda_bf16.h>
#include <math.h>
#include <stdint.h>

#define DD 384
#define HH 192
#define NB 64
#define NATOMS 8192
#define IMG (DD*DD)
#define K1 256            // stage-1 folded K (208) padded to 256
#define MR 192            // rows 0..191 via GEMM; 192 special; 193..383 mirrored

// ---------------- device scratch -------------------------------------------
__device__ float g_sinf[DD];
__device__ __align__(16) __nv_bfloat16 g_Cb_h[MR*K1], g_Cb_l[MR*K1];
__device__ __align__(16) __nv_bfloat16 g_Sb_h[MR*K1], g_Sb_l[MR*K1];
__device__ __align__(16) __nv_bfloat16 g_H1b_h[IMG], g_H1b_l[IMG];
__device__ __align__(16) __nv_bfloat16 g_H2b_h[IMG], g_H2b_l[IMG];
__device__ float g_H1f[IMG];
__device__ __align__(16) __nv_bfloat16 g_XeT_h[NB*DD*K1], g_XeT_l[NB*DD*K1];
__device__ __align__(16) __nv_bfloat16 g_XoT_h[NB*DD*K1], g_XoT_l[NB*DD*K1];
__device__ __align__(16) __nv_bfloat16 g_Trb_h[NB*MR*DD], g_Trb_l[NB*MR*DD];
__device__ __align__(16) __nv_bfloat16 g_Tib_h[NB*MR*DD], g_Tib_l[NB*MR*DD];
__device__ float g_T192[NB*DD];

// ---------------- helpers ----------------------------------------------------
__device__ __forceinline__ void split_bf16(float x, __nv_bfloat16& h, __nv_bfloat16& l) {
    h = __float2bfloat16_rn(x);
    l = __float2bfloat16_rn(x - __bfloat162float(h));
}
__device__ __forceinline__ uint32_t smem_u32(const void* p) {
    uint32_t a;
    asm("{ .reg .u64 t; cvta.to.shared.u64 t, %1; cvt.u32.u64 %0, t; }" : "=r"(a) : "l"(p));
    return a;
}
__device__ __forceinline__ uint32_t swz(uint32_t boff) {
    return boff ^ ((boff >> 3) & 0x70);
}
__device__ __forceinline__ void ldsm_x4(uint32_t addr, uint32_t* r) {
    asm volatile("ldmatrix.sync.aligned.m8n8.x4.shared.b16 {%0,%1,%2,%3}, [%4];"
                 : "=r"(r[0]), "=r"(r[1]), "=r"(r[2]), "=r"(r[3]) : "r"(addr));
}
__device__ __forceinline__ void ldsm_x2(uint32_t addr, uint32_t* r) {
    asm volatile("ldmatrix.sync.aligned.m8n8.x2.shared.b16 {%0,%1}, [%2];"
                 : "=r"(r[0]), "=r"(r[1]) : "r"(addr));
}
__device__ __forceinline__ void mma_bf16(float* c, const uint32_t* a, const uint32_t* b) {
    asm volatile("mma.sync.aligned.m16n8k16.row.col.f32.bf16.bf16.f32 "
                 "{%0,%1,%2,%3},{%4,%5,%6,%7},{%8,%9},{%0,%1,%2,%3};"
                 : "+f"(c[0]), "+f"(c[1]), "+f"(c[2]), "+f"(c[3])
                 : "r"(a[0]), "r"(a[1]), "r"(a[2]), "r"(a[3]), "r"(b[0]), "r"(b[1]));
}
__device__ __forceinline__ void cpasync16(uint32_t dst, const void* src) {
    asm volatile("cp.async.cg.shared.global [%0], [%1], 16;" :: "r"(dst), "l"(src));
}
#define CP_COMMIT() asm volatile("cp.async.commit_group;" ::: "memory")
#define CP_WAIT(n)  asm volatile("cp.async.wait_group %0;" :: "n"(n) : "memory")
__device__ __forceinline__ void red_v4(float* addr, float a, float b, float c, float d) {
    asm volatile("red.global.add.v4.f32 [%0], {%1,%2,%3,%4};"
                 :: "l"(addr), "f"(a), "f"(b), "f"(c), "f"(d) : "memory");
}

// ---------------- tiny sin table (double trig once) --------------------------
__global__ void sintab_kernel() {
    int i = threadIdx.x;
    if (i < DD) g_sinf[i] = (float)sin((double)i * (2.0 * M_PI / (double)DD));
}

// ---------------- all trig tables via gather ---------------------------------
__global__ void tables_kernel() {
    int i = blockIdx.x * blockDim.x + threadIdx.x;
    if (i < MR * K1) {
        int k = i >> 8, u = i & 255;
        float c = 0.f, s = 0.f;
        if (u <= 192) {
            int m = ((k + HH) * (u + HH)) % DD;
            s = g_sinf[m];
            c = g_sinf[(m + 96) % DD];
        }
        split_bf16(c, g_Cb_h[i], g_Cb_l[i]);
        split_bf16(s, g_Sb_h[i], g_Sb_l[i]);
    } else {
        int j = i - MR * K1;
        if (j >= IMG) return;
        int v = j / DD, l = j % DD;
        int m = ((v + HH) * (l + HH)) % DD;
        float s = g_sinf[m];
        float c = g_sinf[(m + 96) % DD];
        split_bf16(c + s, g_H1b_h[j], g_H1b_l[j]);
        split_bf16(c - s, g_H2b_h[j], g_H2b_l[j]);
        g_H1f[j] = c + s;
    }
}

// ---------------- splat: Gaussian recurrence, red.v4 -------------------------
__global__ void splat_kernel(const float* __restrict__ crd,
                             const float* __restrict__ rot,
                             const float* __restrict__ rot_init,
                             const float* __restrict__ trans_init,
                             float* __restrict__ img) {
    int gid = blockIdx.x * blockDim.x + threadIdx.x;
    if (gid < NB * DD) g_T192[gid] = 0.0f;
    if (gid >= NB * NATOMS) return;
    int b = gid >> 13;
    const float* p = crd + (size_t)gid * 3;
    float x0 = p[0], x1 = p[1], x2 = p[2];
    float c0 = x0 * __ldg(&rot_init[0]) + x1 * __ldg(&rot_init[3]) + x2 * __ldg(&rot_init[6]) + __ldg(&trans_init[0]);
    float c1 = x0 * __ldg(&rot_init[1]) + x1 * __ldg(&rot_init[4]) + x2 * __ldg(&rot_init[7]) + __ldg(&trans_init[1]);
    float c2 = x0 * __ldg(&rot_init[2]) + x1 * __ldg(&rot_init[5]) + x2 * __ldg(&rot_init[8]) + __ldg(&trans_init[2]);
    const float* R = rot + b * 9;
    float fx = c0 * __ldg(&R[0]) + c1 * __ldg(&R[1]) + c2 * __ldg(&R[2]);
    float fy = c0 * __ldg(&R[3]) + c1 * __ldg(&R[4]) + c2 * __ldg(&R[5]);
    float cx = fx + (float)HH, cy = fy + (float)HH;
    int ix0 = (int)rintf(cx) - 5, iy0 = (int)rintf(cy) - 5;
    const float A = 1.0f / (2.0f * 1.5f * 1.5f);
    const float C2 = __expf(-2.0f * A);

    int base = ix0 & ~3;
    base = base < 0 ? 0 : (base > DD - 16 ? DD - 16 : base);

    float wx[16];
    float sq[4];
    {
        float d0 = (float)base - cx;
        float g = __expf(-A * d0 * d0);
        float m = __expf(-A * (2.0f * d0 + 1.0f));
#pragma unroll
        for (int j = 0; j < 16; j++) {
            int pos = base + j;
            bool in = (pos >= ix0) && (pos <= ix0 + 10);
            wx[j] = in ? g : 0.0f;
            g *= m;
            m *= C2;
        }
    }
    bool anyx = false;
#pragma unroll
    for (int q = 0; q < 4; q++) {
        sq[q] = wx[q*4] + wx[q*4+1] + wx[q*4+2] + wx[q*4+3];
        anyx |= (sq[q] != 0.f);
    }
    if (!anyx) return;

    float gy[11];
    {
        float e0 = (float)iy0 - cy;
        float g = __expf(-A * e0 * e0);
        float m = __expf(-A * (2.0f * e0 + 1.0f));
#pragma unroll
        for (int t = 0; t < 11; t++) {
            int iy = iy0 + t;
            gy[t] = ((unsigned)iy < (unsigned)DD) ? g : 0.0f;
            g *= m;
            m *= C2;
        }
    }

    float* im = img + (size_t)b * IMG;
#pragma unroll
    for (int ty = 0; ty < 11; ty++) {
        float gyv = gy[ty];
        if (gyv == 0.0f) continue;
        float* rowp = im + (iy0 + ty) * DD + base;
#pragma unroll
        for (int q = 0; q < 4; q++) {
            if (sq[q] != 0.f)
                red_v4(rowp + q * 4, gyv * wx[q*4], gyv * wx[q*4+1], gyv * wx[q*4+2], gyv * wx[q*4+3]);
        }
    }
}

// ---------------- fold + transpose X -> XeT/XoT (+ fused colsum) -------------
__global__ void fold_kernel(const float* __restrict__ X) {
    __shared__ float se[32][33];
    __shared__ float so[32][33];
    int z = blockIdx.z;
    int u0 = blockIdx.y * 32;
    int v0 = blockIdx.x * 32;
    const float* Xb = X + (size_t)z * IMG;
#pragma unroll
    for (int r = 0; r < 4; r++) {
        int uu = u0 + threadIdx.y + r * 8;
        int vv = v0 + threadIdx.x;
        float e = 0.f, o = 0.f;
        if (uu == 0) { e = Xb[vv]; }
        else if (uu < 192) { float a = Xb[uu * DD + vv], bm = Xb[(DD - uu) * DD + vv]; e = a + bm; o = a - bm; }
        else if (uu == 192) { e = Xb[192 * DD + vv]; }
        se[threadIdx.y + r * 8][threadIdx.x] = e;
        so[threadIdx.y + r * 8][threadIdx.x] = o;
    }
    __syncthreads();
    if (threadIdx.y == 0) {
        int vv = v0 + threadIdx.x;
        float acc = 0.f;
#pragma unroll
        for (int i = 0; i < 32; i++) acc += se[i][threadIdx.x];
        if (acc != 0.f || u0 == 0) atomicAdd(&g_T192[z * DD + vv], acc);
    }
#pragma unroll
    for (int r = 0; r < 4; r++) {
        int vv = v0 + threadIdx.y + r * 8;
        int uu = u0 + threadIdx.x;
        if (uu >= 208) continue;
        float e = se[threadIdx.x][threadIdx.y + r * 8];
        float o = so[threadIdx.x][threadIdx.y + r * 8];
        size_t off = ((size_t)z * DD + vv) * K1 + uu;
        split_bf16(e, g_XeT_h[off], g_XeT_l[off]);
        split_bf16(o, g_XoT_h[off], g_XoT_l[off]);
    }
}

// ---------------- row 192 of Y ------------------------------------------------
__global__ void row192_kernel(float* __restrict__ Y) {
    int b = blockIdx.y;
    int l = blockIdx.x * blockDim.x + threadIdx.x;
    if (l >= DD) return;
    const float* t = g_T192 + b * DD;
    float acc = 0.0f;
#pragma unroll 8
    for (int v = 0; v < DD; v++) acc += t[v] * g_H1f[v * DD + l];
    Y[(size_t)b * IMG + 192 * DD + l] = acc;
}

// ---------------- split-precision HMMA GEMM: single-stage, 2 CTAs/SM ---------
// Cross-CTA pipelining: cp.async wait in one CTA overlaps the other CTA's MMAs.
template<int MODE>
__global__ __launch_bounds__(256, 2) void mma_gemm_kernel(float* __restrict__ Y) {
    extern __shared__ char smem[];
    uint32_t sb = smem_u32(smem);
    const int t = threadIdx.x;
    const int lane = t & 31, wid = t >> 5;
    const int wm = wid >> 2, wn = wid & 3;
    const int z = blockIdx.z, m0 = blockIdx.y * 64, n0 = blockIdx.x * 128;

    const int KCH = (MODE == 0) ? 4 : 6;
    const int LD  = (MODE == 0) ? K1 : DD;

    const __nv_bfloat16* Asrc[4];
    const __nv_bfloat16* Bsrc[4];
    if (MODE == 0) {
        Asrc[0] = g_Cb_h + (size_t)m0 * K1;  Asrc[1] = g_Cb_l + (size_t)m0 * K1;
        Asrc[2] = g_Sb_h + (size_t)m0 * K1;  Asrc[3] = g_Sb_l + (size_t)m0 * K1;
        size_t bo = ((size_t)z * DD + n0) * K1;
        Bsrc[0] = g_XeT_h + bo; Bsrc[1] = g_XeT_l + bo;
        Bsrc[2] = g_XoT_h + bo; Bsrc[3] = g_XoT_l + bo;
    } else {
        size_t ao = ((size_t)z * MR + m0) * DD;
        Asrc[0] = g_Trb_h + ao; Asrc[1] = g_Trb_l + ao;
        Asrc[2] = g_Tib_h + ao; Asrc[3] = g_Tib_l + ao;
        size_t bo = (size_t)n0 * DD;
        Bsrc[0] = g_H1b_h + bo; Bsrc[1] = g_H1b_l + bo;
        Bsrc[2] = g_H2b_h + bo; Bsrc[3] = g_H2b_l + bo;
    }

    auto stage = [&](int kc) {
#pragma unroll
        for (int s = 0; s < 4; s++) {
#pragma unroll
            for (int j = 0; j < 2; j++) {
                int cid = t + 256 * j;
                int row = cid >> 3, c = cid & 7;
                cpasync16(sb + s * 8192u + swz((uint32_t)row * 128u + (uint32_t)c * 16u),
                          Asrc[s] + (size_t)row * LD + kc * 64 + c * 8);
            }
#pragma unroll
            for (int j = 0; j < 4; j++) {
                int cid = t + 256 * j;
                int row = cid >> 3, c = cid & 7;
                cpasync16(sb + 32768u + s * 16384u + swz((uint32_t)row * 128u + (uint32_t)c * 16u),
                          Bsrc[s] + (size_t)row * LD + kc * 64 + c * 8);
            }
        }
    };

    float acc[2][2][4][4];
#pragma unroll
    for (int o = 0; o < 2; o++)
#pragma unroll
        for (int mt = 0; mt < 2; mt++)
#pragma unroll
            for (int nt = 0; nt < 4; nt++)
#pragma unroll
                for (int r = 0; r < 4; r++) acc[o][mt][nt][r] = 0.f;

    const int a_row = wm * 32 + (lane & 7) + ((lane >> 3) & 1) * 8;
    const int a_kb  = (lane >> 4) * 16;
    const int b_row = wn * 32 + (lane & 7);
    const int b_kb  = (((lane & 15) >> 3)) * 16;

    for (int kc = 0; kc < KCH; kc++) {
        stage(kc);
        CP_COMMIT();
        CP_WAIT(0);
        __syncthreads();

#pragma unroll
        for (int k16 = 0; k16 < 4; k16++) {
            uint32_t a[4][2][4], b[4][4][2];
#pragma unroll
            for (int s = 0; s < 4; s++)
#pragma unroll
                for (int mt = 0; mt < 2; mt++) {
                    uint32_t bo = (uint32_t)(a_row + mt * 16) * 128u + (uint32_t)(k16 * 32 + a_kb);
                    ldsm_x4(sb + s * 8192u + swz(bo), a[s][mt]);
                }
#pragma unroll
            for (int s = 0; s < 4; s++)
#pragma unroll
                for (int nt = 0; nt < 4; nt++) {
                    uint32_t bo = (uint32_t)(b_row + nt * 8) * 128u + (uint32_t)(k16 * 32 + b_kb);
                    ldsm_x2(sb + 32768u + s * 16384u + swz(bo), b[s][nt]);
                }
#pragma unroll
            for (int mt = 0; mt < 2; mt++)
#pragma unroll
                for (int nt = 0; nt < 4; nt++) {
                    mma_bf16(acc[0][mt][nt], a[0][mt], b[0][nt]);
                    mma_bf16(acc[0][mt][nt], a[0][mt], b[1][nt]);
                    mma_bf16(acc[0][mt][nt], a[1][mt], b[0][nt]);
                    mma_bf16(acc[1][mt][nt], a[2][mt], b[2][nt]);
                    mma_bf16(acc[1][mt][nt], a[2][mt], b[3][nt]);
                    mma_bf16(acc[1][mt][nt], a[3][mt], b[2][nt]);
                }
        }
        __syncthreads();
    }

    const int gr = lane >> 2, gc = 2 * (lane & 3);
    if (MODE == 0) {
#pragma unroll
        for (int mt = 0; mt < 2; mt++)
#pragma unroll
            for (int nt = 0; nt < 4; nt++) {
                int col = n0 + wn * 32 + nt * 8 + gc;
#pragma unroll
                for (int h = 0; h < 2; h++) {
                    int row = m0 + wm * 32 + mt * 16 + gr + h * 8;
                    size_t off = ((size_t)z * MR + row) * DD + col;
                    __nv_bfloat16 h0, l0, h1, l1;
                    split_bf16(acc[0][mt][nt][h * 2],     h0, l0);
                    split_bf16(acc[0][mt][nt][h * 2 + 1], h1, l1);
                    __nv_bfloat162 hh; hh.x = h0; hh.y = h1;
                    __nv_bfloat162 ll; ll.x = l0; ll.y = l1;
                    *reinterpret_cast<__nv_bfloat162*>(&g_Trb_h[off]) = hh;
                    *reinterpret_cast<__nv_bfloat162*>(&g_Trb_l[off]) = ll;
                    split_bf16(acc[1][mt][nt][h * 2],     h0, l0);
                    split_bf16(acc[1][mt][nt][h * 2 + 1], h1, l1);
                    hh.x = h0; hh.y = h1; ll.x = l0; ll.y = l1;
                    *reinterpret_cast<__nv_bfloat162*>(&g_Tib_h[off]) = hh;
                    *reinterpret_cast<__nv_bfloat162*>(&g_Tib_l[off]) = ll;
                }
            }
    } else {
        float* Yb = Y + (size_t)z * IMG;
#pragma unroll
        for (int mt = 0; mt < 2; mt++)
#pragma unroll
            for (int nt = 0; nt < 4; nt++) {
                int col = n0 + wn * 32 + nt * 8 + gc;
#pragma unroll
                for (int h = 0; h < 2; h++) {
                    int row = m0 + wm * 32 + mt * 16 + gr + h * 8;
                    float p0 = acc[0][mt][nt][h * 2],     q0 = acc[1][mt][nt][h * 2];
                    float p1 = acc[0][mt][nt][h * 2 + 1], q1 = acc[1][mt][nt][h * 2 + 1];
                    float2 yp; yp.x = p0 + q0; yp.y = p1 + q1;
                    *reinterpret_cast<float2*>(&Yb[(size_t)row * DD + col]) = yp;
                    if (row >= 1) {
                        float2 ym; ym.x = p0 - q0; ym.y = p1 - q1;
                        *reinterpret_cast<float2*>(&Yb[(size_t)(DD - row) * DD + col]) = ym;
                    }
                }
            }
    }
}

#define SMEM_BYTES 98304

// ---------------------------------------------------------------------------
extern "C" void kernel_launch(void* const* d_in, const int* in_sizes, int n_in,
                              void* d_out, int out_size) {
    const float* crd = nullptr;
    const float* rot = nullptr;
    const float* rot_init = nullptr;
    const float* trans_init = nullptr;
    for (int i = 0; i < n_in; i++) {
        switch (in_sizes[i]) {
            case 1572864: crd        = (const float*)d_in[i]; break;
            case 576:     rot        = (const float*)d_in[i]; break;
            case 9:       rot_init   = (const float*)d_in[i]; break;
            case 3:       trans_init = (const float*)d_in[i]; break;
            default: break;
        }
    }

    float* y = (float*)d_out;
    size_t half = (size_t)out_size / 2;   // 64*384*384
    float* y_real = y + half;

    cudaFuncSetAttribute(mma_gemm_kernel<0>, cudaFuncAttributeMaxDynamicSharedMemorySize, SMEM_BYTES);
    cudaFuncSetAttribute(mma_gemm_kernel<1>, cudaFuncAttributeMaxDynamicSharedMemorySize, SMEM_BYTES);

    // Fork-join: [sintab -> tables] runs parallel to [memset -> splat -> fold]
    cudaStream_t s2;
    cudaStreamCreateWithFlags(&s2, cudaStreamNonBlocking);
    cudaEvent_t ev_fork, ev_join;
    cudaEventCreateWithFlags(&ev_fork, cudaEventDisableTiming);
    cudaEventCreateWithFlags(&ev_join, cudaEventDisableTiming);

    cudaMemsetAsync(y_real, 0, half * sizeof(float));

    cudaEventRecord(ev_fork, (cudaStream_t)0);
    cudaStreamWaitEvent(s2, ev_fork, 0);
    sintab_kernel<<<1, 384, 0, s2>>>();
    tables_kernel<<<(MR * K1 + IMG + 255) / 256, 256, 0, s2>>>();
    cudaEventRecord(ev_join, s2);

    splat_kernel<<<(NB * NATOMS + 255) / 256, 256>>>(crd, rot, rot_init, trans_init, y_real);
    dim3 gf(DD / 32, 7, NB);
    fold_kernel<<<gf, dim3(32, 8)>>>(y_real);

    cudaStreamWaitEvent((cudaStream_t)0, ev_join, 0);

    dim3 gg(DD / 128, MR / 64, NB);       // 3 x 3 x 64
    mma_gemm_kernel<0><<<gg, 256, SMEM_BYTES>>>(nullptr);
    mma_gemm_kernel<1><<<gg, 256, SMEM_BYTES>>>(y);

    dim3 gr((DD + 127) / 128, NB);
    row192_kernel<<<gr, 128>>>(y);

    cudaStreamDestroy(s2);
    cudaEventDestroy(ev_fork);
    cudaEventDestroy(ev_join);
}